// round 3
// baseline (speedup 1.0000x reference)
#include <cuda_runtime.h>
#include <cuda_bf16.h>

#define FM      14
#define HW      196          // 14*14
#define CH      2048
#define NWIN    361

#define GROUPS  8
#define NTHR    (GROUPS * 49)   // 392

#define NEG_INF __int_as_float(0xff800000)

__device__ __forceinline__ float pick4(const float a[4], int kk) {
    float r = a[0];
    if (kk == 1) r = a[1];
    if (kk == 2) r = a[2];
    if (kk == 3) r = a[3];
    return r;
}

// ---------------------------------------------------------------------------
// Fused kernel: one block per batch.
//   Phase 1: stream 2048x196 floats (1.6 MB), channel-sum into shared.
//   Phase 2: 361 window avg-pools.
//   Phase 3: greedy NMS (3 warps, one per ratio group).
// Output layout (fp32): [B*7 indices][B*7 window scores][B*361 all_scores]
// ---------------------------------------------------------------------------
__global__ __launch_bounds__(NTHR) void appm_fused_kernel(
    const float* __restrict__ x, const int* __restrict__ coords,
    float* __restrict__ out, int B)
{
    const int b   = blockIdx.x;
    const int tid = threadIdx.x;           // 0..391
    const int grp = tid / 49;              // 0..7  (channel sub-slice)
    const int v   = tid - grp * 49;        // 0..48 (float4 index in a 196-float map)

    __shared__ float4 red[GROUPS * 49];
    __shared__ float  ssum[HW];
    __shared__ float  scores[NWIN];
    __shared__ float  cbox[NWIN * 4];
    __shared__ int    sel_idx[7];
    __shared__ float  sel_sc[7];

    // Load coordinates early (tiny; overlaps with the big stream).
    for (int i = tid; i < NWIN * 4; i += NTHR) cbox[i] = (float)coords[i];

    // ---- Phase 1: channel-sum stream --------------------------------------
    const float4* base = reinterpret_cast<const float4*>(x + (size_t)b * CH * HW);

    float4 acc = make_float4(0.f, 0.f, 0.f, 0.f);
#pragma unroll 16
    for (int c = grp; c < CH; c += GROUPS) {
        float4 t = base[c * 49 + v];
        acc.x += t.x; acc.y += t.y; acc.z += t.z; acc.w += t.w;
    }
    red[grp * 49 + v] = acc;
    __syncthreads();

    if (tid < HW) {
        const float* rf = reinterpret_cast<const float*>(red);
        float s = 0.f;
#pragma unroll
        for (int g = 0; g < GROUPS; g++) s += rf[g * HW + tid];
        ssum[tid] = s;
    }
    __syncthreads();

    // ---- Phase 2: window scores -------------------------------------------
    float* all_scores_out = out + 14 * B;   // after indices[B*7] + scores[B*7]
    for (int w = tid; w < NWIN; w += NTHR) {
        int i, j, rh, rw;
        if (w < 121)      { rh = 4; rw = 4; int l = w;       i = l / 11; j = l % 11; }
        else if (w < 241) { rh = 3; rw = 5; int l = w - 121; i = l / 10; j = l % 10; }
        else              { rh = 5; rw = 3; int l = w - 241; i = l / 12; j = l % 12; }
        float s = 0.f;
        for (int di = 0; di < rh; di++)
            for (int dj = 0; dj < rw; dj++)
                s += ssum[(i + di) * FM + (j + dj)];
        s /= (float)(rh * rw);
        scores[w] = s;
        all_scores_out[b * NWIN + w] = s;
    }
    __syncthreads();

    // ---- Phase 3: greedy NMS, warp g handles group g ----------------------
    const int wid  = tid >> 5;
    const int lane = tid & 31;
    if (wid < 3) {
        const int starts[3] = {0, 121, 241};
        const int counts[3] = {121, 120, 120};
        const int ns[3]     = {2, 3, 2};
        const int outoff[3] = {0, 2, 5};
        const float thresh  = 0.25f;

        const int st  = starts[wid];
        const int cnt = counts[wid];
        const int n   = ns[wid];

        float sc[4], x0[4], y0[4], x1[4], y1[4];
        bool  alive[4];
#pragma unroll
        for (int k = 0; k < 4; k++) {
            int ii = k * 32 + lane;
            bool valid = (ii < cnt);
            alive[k] = valid;
            int gi = st + (valid ? ii : 0);
            sc[k] = valid ? scores[gi] : 0.f;
            x0[k] = cbox[gi * 4 + 0];
            y0[k] = cbox[gi * 4 + 1];
            x1[k] = cbox[gi * 4 + 2];
            y1[k] = cbox[gi * 4 + 3];
        }

        for (int step = 0; step < n; step++) {
            // argmax over where(alive, sc, -inf); first-index tie-break.
            float bv = NEG_INF;
            int   bi = 0x7FFFFFFF;
#pragma unroll
            for (int k = 0; k < 4; k++) {
                float vkv = alive[k] ? sc[k] : NEG_INF;
                int   vki = k * 32 + lane;
                if (vki < cnt && (vkv > bv || (vkv == bv && vki < bi))) { bv = vkv; bi = vki; }
            }
#pragma unroll
            for (int off = 16; off > 0; off >>= 1) {
                float ov = __shfl_down_sync(0xFFFFFFFFu, bv, off);
                int   oi = __shfl_down_sync(0xFFFFFFFFu, bi, off);
                if (ov > bv || (ov == bv && oi < bi)) { bv = ov; bi = oi; }
            }
            bi = __shfl_sync(0xFFFFFFFFu, bi, 0);

            if (lane == 0) {
                sel_idx[outoff[wid] + step] = st + bi;
                sel_sc [outoff[wid] + step] = scores[st + bi];
            }

            const int kk = bi >> 5;
            const int srcLane = bi & 31;
            float BX0 = __shfl_sync(0xFFFFFFFFu, pick4(x0, kk), srcLane);
            float BY0 = __shfl_sync(0xFFFFFFFFu, pick4(y0, kk), srcLane);
            float BX1 = __shfl_sync(0xFFFFFFFFu, pick4(x1, kk), srcLane);
            float BY1 = __shfl_sync(0xFFFFFFFFu, pick4(y1, kk), srcLane);
            float areaB = (BX1 - BX0) * (BY1 - BY0);

#pragma unroll
            for (int k = 0; k < 4; k++) {
                float ix0 = fmaxf(BX0, x0[k]);
                float iy0 = fmaxf(BY0, y0[k]);
                float ix1 = fminf(BX1, x1[k]);
                float iy1 = fminf(BY1, y1[k]);
                float inter = fmaxf(ix1 - ix0, 0.f) * fmaxf(iy1 - iy0, 0.f);
                float areaK = (x1[k] - x0[k]) * (y1[k] - y0[k]);
                float iou = inter / (areaB + areaK - inter);
                if (!(iou < thresh)) alive[k] = false;
            }
        }
    }
    __syncthreads();

    // ---- Outputs: indices (as float) and the 7 selected scores ------------
    if (tid < 7) {
        out[b * 7 + tid]         = (float)sel_idx[tid];
        out[7 * B + b * 7 + tid] = sel_sc[tid];
    }
}

extern "C" void kernel_launch(void* const* d_in, const int* in_sizes, int n_in,
                              void* d_out, int out_size) {
    const float* x      = (const float*)d_in[0];
    const int*   coords = (const int*)d_in[1];
    float*       out    = (float*)d_out;

    const int B = in_sizes[0] / (CH * HW);   // 64

    appm_fused_kernel<<<B, NTHR>>>(x, coords, out, B);
}

// round 4
// speedup vs baseline: 1.2861x; 1.2861x over previous
#include <cuda_runtime.h>
#include <cuda_bf16.h>

#define FM      14
#define HW      196          // 14*14
#define CH      2048
#define CHUNKS  16
#define CPC     (CH / CHUNKS)   // 128 channels per chunk
#define NWIN    361
#define MAXB    64
#define NTHR    196

#define NEG_INF __int_as_float(0xff800000)

// Partial channel sums: [chunk][batch][hw]. Fully overwritten every run.
__device__ float g_part[CHUNKS * MAXB * HW];
// Per-batch arrival counters. Zero at load; reset to zero by the finalizing
// block each run, so graph replays are deterministic.
__device__ int g_count[MAXB];

__device__ __forceinline__ float pick4(const float a[4], int kk) {
    float r = a[0];
    if (kk == 1) r = a[1];
    if (kk == 2) r = a[2];
    if (kk == 3) r = a[3];
    return r;
}

// ---------------------------------------------------------------------------
// One kernel. grid = (B, CHUNKS). Each block channel-sums its 128-channel
// slice of one batch. The last block to finish a batch (arrival counter)
// performs the finalize: partial-sum, window scores, greedy NMS, outputs.
// Output layout (fp32): [B*7 indices][B*7 window scores][B*361 all_scores]
// ---------------------------------------------------------------------------
__global__ __launch_bounds__(NTHR) void appm_kernel(
    const float* __restrict__ x, const int* __restrict__ coords,
    float* __restrict__ out, int B)
{
    const int b     = blockIdx.x;
    const int chunk = blockIdx.y;
    const int tid   = threadIdx.x;          // 0..195
    const int grp   = tid / 49;             // 0..3
    const int v     = tid - grp * 49;       // 0..48

    __shared__ float4 red[4 * 49];
    __shared__ int    s_last;

    // ---- Phase 1: channel-sum this (batch, chunk) slice -------------------
    const float4* base = reinterpret_cast<const float4*>(
        x + ((size_t)b * CH + (size_t)chunk * CPC) * HW);

    float4 acc = make_float4(0.f, 0.f, 0.f, 0.f);
#pragma unroll 8
    for (int c = grp; c < CPC; c += 4) {
        float4 t = base[c * 49 + v];
        acc.x += t.x; acc.y += t.y; acc.z += t.z; acc.w += t.w;
    }
    red[grp * 49 + v] = acc;
    __syncthreads();

    if (tid < HW) {
        const float* rf = reinterpret_cast<const float*>(red);
        g_part[(chunk * B + b) * HW + tid] =
            rf[tid] + rf[HW + tid] + rf[2 * HW + tid] + rf[3 * HW + tid];
    }

    // ---- Arrival: last block for this batch does the epilogue -------------
    __threadfence();   // release: make g_part writes visible before counting
    __syncthreads();
    if (tid == 0) {
        int old = atomicAdd(&g_count[b], 1);
        s_last = (old == CHUNKS - 1);
    }
    __syncthreads();
    if (!s_last) return;
    if (tid == 0) g_count[b] = 0;   // reset for next graph replay
    __threadfence();                // acquire: see all chunks' g_part writes

    // ---- Phase 2: finalize -------------------------------------------------
    __shared__ float ssum[HW];
    __shared__ float scores[NWIN];
    __shared__ float cbox[NWIN * 4];
    __shared__ int   sel_idx[7];
    __shared__ float sel_sc[7];

    for (int i = tid; i < NWIN * 4; i += NTHR) cbox[i] = (float)coords[i];

    {
        float s = 0.f;
#pragma unroll
        for (int k = 0; k < CHUNKS; k++) s += g_part[(k * B + b) * HW + tid];
        ssum[tid] = s;
    }
    __syncthreads();

    float* all_scores_out = out + 14 * B;   // after indices[B*7] + scores[B*7]
    for (int w = tid; w < NWIN; w += NTHR) {
        int i, j, rh, rw;
        if (w < 121)      { rh = 4; rw = 4; int l = w;       i = l / 11; j = l % 11; }
        else if (w < 241) { rh = 3; rw = 5; int l = w - 121; i = l / 10; j = l % 10; }
        else              { rh = 5; rw = 3; int l = w - 241; i = l / 12; j = l % 12; }
        float s = 0.f;
        for (int di = 0; di < rh; di++)
            for (int dj = 0; dj < rw; dj++)
                s += ssum[(i + di) * FM + (j + dj)];
        s /= (float)(rh * rw);
        scores[w] = s;
        all_scores_out[b * NWIN + w] = s;
    }
    __syncthreads();

    // ---- Phase 3: greedy NMS, warp g handles group g ----------------------
    const int wid  = tid >> 5;
    const int lane = tid & 31;
    if (wid < 3) {
        const int starts[3] = {0, 121, 241};
        const int counts[3] = {121, 120, 120};
        const int ns[3]     = {2, 3, 2};
        const int outoff[3] = {0, 2, 5};
        const float thresh  = 0.25f;

        const int st  = starts[wid];
        const int cnt = counts[wid];
        const int n   = ns[wid];

        float sc[4], x0[4], y0[4], x1[4], y1[4];
        bool  alive[4];
#pragma unroll
        for (int k = 0; k < 4; k++) {
            int ii = k * 32 + lane;
            bool valid = (ii < cnt);
            alive[k] = valid;
            int gi = st + (valid ? ii : 0);
            sc[k] = valid ? scores[gi] : 0.f;
            x0[k] = cbox[gi * 4 + 0];
            y0[k] = cbox[gi * 4 + 1];
            x1[k] = cbox[gi * 4 + 2];
            y1[k] = cbox[gi * 4 + 3];
        }

        for (int step = 0; step < n; step++) {
            float bv = NEG_INF;
            int   bi = 0x7FFFFFFF;
#pragma unroll
            for (int k = 0; k < 4; k++) {
                float vkv = alive[k] ? sc[k] : NEG_INF;
                int   vki = k * 32 + lane;
                if (vki < cnt && (vkv > bv || (vkv == bv && vki < bi))) { bv = vkv; bi = vki; }
            }
#pragma unroll
            for (int off = 16; off > 0; off >>= 1) {
                float ov = __shfl_down_sync(0xFFFFFFFFu, bv, off);
                int   oi = __shfl_down_sync(0xFFFFFFFFu, bi, off);
                if (ov > bv || (ov == bv && oi < bi)) { bv = ov; bi = oi; }
            }
            bi = __shfl_sync(0xFFFFFFFFu, bi, 0);

            if (lane == 0) {
                sel_idx[outoff[wid] + step] = st + bi;
                sel_sc [outoff[wid] + step] = scores[st + bi];
            }

            const int kk = bi >> 5;
            const int srcLane = bi & 31;
            float BX0 = __shfl_sync(0xFFFFFFFFu, pick4(x0, kk), srcLane);
            float BY0 = __shfl_sync(0xFFFFFFFFu, pick4(y0, kk), srcLane);
            float BX1 = __shfl_sync(0xFFFFFFFFu, pick4(x1, kk), srcLane);
            float BY1 = __shfl_sync(0xFFFFFFFFu, pick4(y1, kk), srcLane);
            float areaB = (BX1 - BX0) * (BY1 - BY0);

#pragma unroll
            for (int k = 0; k < 4; k++) {
                float ix0 = fmaxf(BX0, x0[k]);
                float iy0 = fmaxf(BY0, y0[k]);
                float ix1 = fminf(BX1, x1[k]);
                float iy1 = fminf(BY1, y1[k]);
                float inter = fmaxf(ix1 - ix0, 0.f) * fmaxf(iy1 - iy0, 0.f);
                float areaK = (x1[k] - x0[k]) * (y1[k] - y0[k]);
                float iou = inter / (areaB + areaK - inter);
                if (!(iou < thresh)) alive[k] = false;
            }
        }
    }
    __syncthreads();

    if (tid < 7) {
        out[b * 7 + tid]         = (float)sel_idx[tid];
        out[7 * B + b * 7 + tid] = sel_sc[tid];
    }
}

extern "C" void kernel_launch(void* const* d_in, const int* in_sizes, int n_in,
                              void* d_out, int out_size) {
    const float* x      = (const float*)d_in[0];
    const int*   coords = (const int*)d_in[1];
    float*       out    = (float*)d_out;

    const int B = in_sizes[0] / (CH * HW);   // 64

    dim3 grid(B, CHUNKS);
    appm_kernel<<<grid, NTHR>>>(x, coords, out, B);
}